// round 15
// baseline (speedup 1.0000x reference)
#include <cuda_runtime.h>
#include <cstdint>

// FilterAugment: out[b,f,t] = x[b,f,t] * 10^(gain_db(b,f)/20)
// B=64, F=256, T=2048 (fp32). HBM-bound stream.
//
// R15 = R11 skeleton with the prefetch retargeted ONE WAVE AHEAD.
// Own-tile prefetch only led the LDGs by the gain-compute preamble
// (~100cyc << DRAM ~400-600cyc) — hence its modest ~1us win. Wave size =
// 148 SMs x occ 8 = 1184 CTAs; CTA bid prefetches the tile of bid+1184,
// which runs ~5us later on ~the same SM: full latency hide for waves 1+.
// In-flight prefetch footprint 1184 x 16KiB = 18.5 MiB << 126 MB L2.
// Noise note: harness dur_us has +-1.5us run-to-run variance (R11 vs R14,
// identical source: 43.52 vs 45.12); flushed ncu time is the discriminator.

#define F_DIM        256
#define T_DIM        2048
#define NBP1         5              // N_BAND + 1
#define ROWS_PER_CTA 2
#define V4_PER_ROW   (T_DIM / 4)    // 512
#define DB_TO_LOG2   0.166096404744368f   // log2(10)/20
#define WAVE_CTAS    1184           // 148 SMs * occ 8

__global__ __launch_bounds__(256, 8)
void filter_augment_kernel(const float4* __restrict__ x,
                           const float*  __restrict__ band_factors,
                           const int*    __restrict__ bndry,
                           float4* __restrict__ out)
{
    const int base_row = blockIdx.x * ROWS_PER_CTA;
    const int tid = threadIdx.x;

    const size_t base4 = (size_t)base_row * V4_PER_ROW;
    const float4* __restrict__ in4  = x   + base4;
    float4* __restrict__       out4 = out + base4;

    // Prefetch the input tile of the CTA one wave ahead (bid + 1184):
    // by the time that CTA issues its loads (~5us from now), its 16 KiB
    // tile (128 x 128B lines, threads 0..127 one line each) is L2-resident.
    {
        int pf_blk = blockIdx.x + WAVE_CTAS;
        if (pf_blk >= (int)gridDim.x) pf_blk = blockIdx.x;   // edge: own tile
        if (tid < 128) {
            const char* p = reinterpret_cast<const char*>(x)
                          + (size_t)pf_blk * (ROWS_PER_CTA * T_DIM * 4)
                          + tid * 128;
            asm volatile("prefetch.global.L2::evict_last [%0];" :: "l"(p));
        }
    }

    // Boundaries (tiny, cached)
    int bd[NBP1];
    #pragma unroll
    for (int j = 0; j < NBP1; ++j) bd[j] = __ldg(&bndry[j]);

    // Per-row gains, computed redundantly by every thread (2x exp2f, trivial).
    float filt[ROWS_PER_CTA];
    #pragma unroll
    for (int j = 0; j < ROWS_PER_CTA; ++j) {
        const int row = base_row + j;
        const int f = row & (F_DIM - 1);
        const int b = row >> 8;            // F=256

        // searchsorted(bndry, f, 'right') - 1 clipped to [0, NBP1-2]
        int idx = 0;
        #pragma unroll
        for (int k = 1; k < NBP1; ++k)
            idx += (f >= bd[k]) ? 1 : 0;
        if (idx > NBP1 - 2) idx = NBP1 - 2;

        const int lo    = bd[idx];
        const int width = bd[idx + 1] - lo;
        const float denom = (float)max(width - 1, 1);
        const float t = (float)(f - lo) / denom;

        const float g0 = __ldg(&band_factors[b * NBP1 + idx]);
        const float g1 = __ldg(&band_factors[b * NBP1 + idx + 1]);
        const float gain_db = fmaf(g1 - g0, t, g0);
        filt[j] = exp2f(gain_db * DB_TO_LOG2);
    }

    // Stream 2 rows = 1024 float4: 256 threads x 4 iters, batched loads (MLP=4).
    float4 v[4];
    #pragma unroll
    for (int i = 0; i < 4; ++i)
        v[i] = in4[i * 256 + tid];

    #pragma unroll
    for (int i = 0; i < 4; ++i) {
        const float g = filt[i >> 1];
        v[i].x *= g; v[i].y *= g; v[i].z *= g; v[i].w *= g;
        // Evict-first store: output lines evict each other, not the
        // evict_last-marked input.
        __stcs(&out4[i * 256 + tid], v[i]);
    }
}

extern "C" void kernel_launch(void* const* d_in, const int* in_sizes, int n_in,
                              void* d_out, int out_size)
{
    const float4* features    = (const float4*)d_in[0];
    const float* band_factors = (const float*)d_in[1];
    const int*   bndry        = (const int*)d_in[2];
    float4* out = (float4*)d_out;

    const int B = in_sizes[1] / NBP1;            // band_factors: B*(N_BAND+1)
    const int nrows = B * F_DIM;
    const int nblocks = nrows / ROWS_PER_CTA;

    filter_augment_kernel<<<nblocks, 256>>>(features, band_factors, bndry, out);
}

// round 16
// speedup vs baseline: 1.0554x; 1.0554x over previous
#include <cuda_runtime.h>
#include <cstdint>

// FilterAugment: out[b,f,t] = x[b,f,t] * 10^(gain_db(b,f)/20)
// B=64, F=256, T=2048 (fp32). Pure HBM-bound stream.
//
// FINAL (R11 variant — best min and mean across 15 rounds of measurement).
//  - 2 rows/CTA, 8192 CTAs x 256 thr, 4 batched LDG.128 (MLP=4): sharp
//    optimum, bracketed by MLP=2/8/16 measurements.
//  - prefetch.global.L2::evict_last of the CTA's own 16 KiB input tile:
//    consistent ~1us flushed win (software prefetch) + input L2 pinning.
//  - __stcs evict-first stores: write-back speed; output lines evict each
//    other rather than the evict_last-pinned input.
// Rejected with evidence: persistent grid-stride, wt stores, L2-discard of
// dead output, one-wave-ahead prefetch, larger tiles, 256-bit load path.
// Achieved ~6.8 TB/s effective vs logical traffic in the warm steady state
// — the practical roofline for this read+write interleaved stream.

#define F_DIM        256
#define T_DIM        2048
#define NBP1         5              // N_BAND + 1
#define ROWS_PER_CTA 2
#define V4_PER_ROW   (T_DIM / 4)    // 512
#define DB_TO_LOG2   0.166096404744368f   // log2(10)/20

__global__ __launch_bounds__(256, 8)
void filter_augment_kernel(const float4* __restrict__ x,
                           const float*  __restrict__ band_factors,
                           const int*    __restrict__ bndry,
                           float4* __restrict__ out)
{
    const int base_row = blockIdx.x * ROWS_PER_CTA;
    const int tid = threadIdx.x;

    const size_t base4 = (size_t)base_row * V4_PER_ROW;
    const float4* __restrict__ in4  = x   + base4;
    float4* __restrict__       out4 = out + base4;

    // Software-prefetch this CTA's 16 KiB input tile (128 x 128B lines;
    // threads 0..127 issue one line each), marked evict_last.
    if (tid < 128) {
        const char* p = reinterpret_cast<const char*>(in4) + tid * 128;
        asm volatile("prefetch.global.L2::evict_last [%0];" :: "l"(p));
    }

    // Boundaries (tiny, cached)
    int bd[NBP1];
    #pragma unroll
    for (int j = 0; j < NBP1; ++j) bd[j] = __ldg(&bndry[j]);

    // Per-row gains, computed redundantly by every thread (2x exp2f, trivial).
    float filt[ROWS_PER_CTA];
    #pragma unroll
    for (int j = 0; j < ROWS_PER_CTA; ++j) {
        const int row = base_row + j;
        const int f = row & (F_DIM - 1);
        const int b = row >> 8;            // F=256

        // searchsorted(bndry, f, 'right') - 1 clipped to [0, NBP1-2]
        int idx = 0;
        #pragma unroll
        for (int k = 1; k < NBP1; ++k)
            idx += (f >= bd[k]) ? 1 : 0;
        if (idx > NBP1 - 2) idx = NBP1 - 2;

        const int lo    = bd[idx];
        const int width = bd[idx + 1] - lo;
        const float denom = (float)max(width - 1, 1);
        const float t = (float)(f - lo) / denom;

        const float g0 = __ldg(&band_factors[b * NBP1 + idx]);
        const float g1 = __ldg(&band_factors[b * NBP1 + idx + 1]);
        const float gain_db = fmaf(g1 - g0, t, g0);
        filt[j] = exp2f(gain_db * DB_TO_LOG2);
    }

    // Stream 2 rows = 1024 float4: 256 threads x 4 iters, batched loads (MLP=4).
    float4 v[4];
    #pragma unroll
    for (int i = 0; i < 4; ++i)
        v[i] = in4[i * 256 + tid];

    #pragma unroll
    for (int i = 0; i < 4; ++i) {
        const float g = filt[i >> 1];
        v[i].x *= g; v[i].y *= g; v[i].z *= g; v[i].w *= g;
        // Evict-first store: write-back speed, minimal L2 retention —
        // output lines evict each other, not the evict_last input.
        __stcs(&out4[i * 256 + tid], v[i]);
    }
}

extern "C" void kernel_launch(void* const* d_in, const int* in_sizes, int n_in,
                              void* d_out, int out_size)
{
    const float4* features    = (const float4*)d_in[0];
    const float* band_factors = (const float*)d_in[1];
    const int*   bndry        = (const int*)d_in[2];
    float4* out = (float4*)d_out;

    const int B = in_sizes[1] / NBP1;            // band_factors: B*(N_BAND+1)
    const int nrows = B * F_DIM;
    const int nblocks = nrows / ROWS_PER_CTA;

    filter_augment_kernel<<<nblocks, 256>>>(features, band_factors, bndry, out);
}

// round 17
// speedup vs baseline: 1.0561x; 1.0007x over previous
#include <cuda_runtime.h>
#include <cstdint>

// FilterAugment: out[b,f,t] = x[b,f,t] * 10^(gain_db(b,f)/20)
// B=64, F=256, T=2048 (fp32). Pure HBM-bound stream.
//
// R17: last untested structural variable — block size. 512 threads/block,
// 4 rows/CTA, 4096 CTAs. Per-THREAD memory profile is bit-identical to the
// verified optimum (4 batched LDG.128 within a 2-row half, MLP=4; threads
// 0-255 own rows 0-1, threads 256-511 own rows 2-3; threads/SM unchanged
// at 2048, so per-SM load-queue pressure is identical). Halves CTA count
// -> halves per-CTA preamble executions and launch/drain overhead.
// Keeps: prefetch.L2::evict_last own tile, __stcs stores (family best).

#define F_DIM        256
#define T_DIM        2048
#define NBP1         5              // N_BAND + 1
#define ROWS_PER_CTA 4
#define V4_PER_ROW   (T_DIM / 4)    // 512
#define DB_TO_LOG2   0.166096404744368f   // log2(10)/20

__global__ __launch_bounds__(512, 4)
void filter_augment_kernel(const float4* __restrict__ x,
                           const float*  __restrict__ band_factors,
                           const int*    __restrict__ bndry,
                           float4* __restrict__ out)
{
    const int tid  = threadIdx.x;
    const int half = tid >> 8;            // 0: rows 0-1, 1: rows 2-3
    const int htid = tid & 255;           // thread id within the half

    const int base_row = blockIdx.x * ROWS_PER_CTA + half * 2;

    // This half's 2-row slice (16 KiB), exactly like an R3 CTA tile.
    const size_t base4 = (size_t)base_row * V4_PER_ROW;
    const float4* __restrict__ in4  = x   + base4;
    float4* __restrict__       out4 = out + base4;

    // Prefetch the CTA's 32 KiB input tile: 256 x 128B lines; threads
    // 0..127 of EACH half prefetch their half's 128 lines (evict_last).
    if (htid < 128) {
        const char* p = reinterpret_cast<const char*>(in4) + htid * 128;
        asm volatile("prefetch.global.L2::evict_last [%0];" :: "l"(p));
    }

    // Boundaries (tiny, cached)
    int bd[NBP1];
    #pragma unroll
    for (int j = 0; j < NBP1; ++j) bd[j] = __ldg(&bndry[j]);

    // Gains for this thread's own 2 rows only.
    float filt[2];
    #pragma unroll
    for (int j = 0; j < 2; ++j) {
        const int row = base_row + j;
        const int f = row & (F_DIM - 1);
        const int b = row >> 8;            // F=256

        // searchsorted(bndry, f, 'right') - 1 clipped to [0, NBP1-2]
        int idx = 0;
        #pragma unroll
        for (int k = 1; k < NBP1; ++k)
            idx += (f >= bd[k]) ? 1 : 0;
        if (idx > NBP1 - 2) idx = NBP1 - 2;

        const int lo    = bd[idx];
        const int width = bd[idx + 1] - lo;
        const float denom = (float)max(width - 1, 1);
        const float t = (float)(f - lo) / denom;

        const float g0 = __ldg(&band_factors[b * NBP1 + idx]);
        const float g1 = __ldg(&band_factors[b * NBP1 + idx + 1]);
        const float gain_db = fmaf(g1 - g0, t, g0);
        filt[j] = exp2f(gain_db * DB_TO_LOG2);
    }

    // Stream this half's 2 rows = 1024 float4: 256 threads x 4 iters,
    // batched loads (MLP=4). Element i*256+htid is in row i>>1.
    float4 v[4];
    #pragma unroll
    for (int i = 0; i < 4; ++i)
        v[i] = in4[i * 256 + htid];

    #pragma unroll
    for (int i = 0; i < 4; ++i) {
        const float g = filt[i >> 1];
        v[i].x *= g; v[i].y *= g; v[i].z *= g; v[i].w *= g;
        // Evict-first store: output lines evict each other, not the
        // evict_last-pinned input.
        __stcs(&out4[i * 256 + htid], v[i]);
    }
}

extern "C" void kernel_launch(void* const* d_in, const int* in_sizes, int n_in,
                              void* d_out, int out_size)
{
    const float4* features    = (const float4*)d_in[0];
    const float* band_factors = (const float*)d_in[1];
    const int*   bndry        = (const int*)d_in[2];
    float4* out = (float4*)d_out;

    const int B = in_sizes[1] / NBP1;            // band_factors: B*(N_BAND+1)
    const int nrows = B * F_DIM;
    const int nblocks = nrows / ROWS_PER_CTA;

    filter_augment_kernel<<<nblocks, 512>>>(features, band_factors, bndry, out);
}